// round 7
// baseline (speedup 1.0000x reference)
#include <cuda_runtime.h>
#include <cuda_bf16.h>
#include <math.h>

#define NN      50000
#define NE      800000
#define F0      64
#define F1      128
#define F2      32
#define SCAN_B  1024
#define NBLK    ((NN + SCAN_B - 1) / SCAN_B)   // 49

// ---------------- scratch (static device globals) ----------------------------
__device__ float g_ax[NN * F0];     // aggregated x
__device__ float g_a1[NN * F1];     // relu(agg(x) @ W1 + b1)
__device__ float g_h2[NN * F2];     // a1 @ W2
__device__ float g_dinv[NN];
__device__ int   g_cnt[NN];         // zero at load; self-zeroed by k_scan1 each run
__device__ int   g_fill[NN];
__device__ int   g_rowptr[NN + 1];
__device__ int   g_blksum[64];
__device__ int   g_colsrc[NE];

// ---------------- packed f32x2 helpers --------------------------------------
__device__ __forceinline__ void ffma2(unsigned long long& d,
                                      unsigned long long a,
                                      unsigned long long b) {
    asm("fma.rn.f32x2 %0, %1, %2, %0;" : "+l"(d) : "l"(a), "l"(b));
}
__device__ __forceinline__ unsigned long long pack2(float x, float y) {
    unsigned long long r;
    asm("mov.b64 %0, {%1, %2};" : "=l"(r) : "f"(x), "f"(y));
    return r;
}
__device__ __forceinline__ void unpack2(unsigned long long v, float& x, float& y) {
    asm("mov.b64 {%0, %1}, %2;" : "=f"(x), "=f"(y) : "l"(v));
}

// ---------------- CSR build --------------------------------------------------
__global__ void k_count(const int* __restrict__ dst) {
    int e = blockIdx.x * blockDim.x + threadIdx.x;
    if (e < NE) atomicAdd(&g_cnt[dst[e]], 1);
}

__global__ void k_scan1() {
    __shared__ int s[SCAN_B];
    int tid = threadIdx.x;
    int i = blockIdx.x * SCAN_B + tid;
    int v = 0;
    if (i < NN) {
        v = g_cnt[i];
        g_cnt[i] = 0;                                 // reset for next replay
        g_dinv[i] = rsqrtf((float)(v + 1));           // +1 self loop
    }
    s[tid] = v;
    __syncthreads();
    #pragma unroll
    for (int off = 1; off < SCAN_B; off <<= 1) {
        int t = (tid >= off) ? s[tid - off] : 0;
        __syncthreads();
        s[tid] += t;
        __syncthreads();
    }
    if (i < NN) g_rowptr[i] = s[tid] - v;
    if (tid == SCAN_B - 1) g_blksum[blockIdx.x] = s[tid];
}

// scan3 with block-local re-scan of the 49 block sums (k_scan2 eliminated)
__global__ void __launch_bounds__(256) k_scan3() {
    __shared__ int s[64];
    int t = threadIdx.x;
    int v = 0;
    if (t < 64) {
        v = (t < NBLK) ? g_blksum[t] : 0;
        s[t] = v;
    }
    __syncthreads();
    #pragma unroll
    for (int off = 1; off < 64; off <<= 1) {
        int u = (t < 64 && t >= off) ? s[t - off] : 0;
        __syncthreads();
        if (t < 64) s[t] += u;
        __syncthreads();
    }
    // s[] now inclusive prefix of block sums
    int i = blockIdx.x * 256 + t;
    if (i < NN) {
        int blk = i >> 10;
        int add = blk ? s[blk - 1] : 0;
        int r = g_rowptr[i] + add;
        g_rowptr[i] = r;
        g_fill[i] = r;
    }
    if (i == 0) g_rowptr[NN] = NE;
}

__global__ void k_scatter(const int* __restrict__ src, const int* __restrict__ dst) {
    int e = blockIdx.x * blockDim.x + threadIdx.x;
    if (e < NE) {
        int pos = atomicAdd(&g_fill[dst[e]], 1);
        g_colsrc[pos] = src[e];
    }
}

// ---------------- Aggregate x (F=64, warp per node, float2, unroll 8) --------
__global__ void __launch_bounds__(256) k_aggx(const float* __restrict__ x) {
    int gtid = blockIdx.x * blockDim.x + threadIdx.x;
    int n = gtid >> 5;
    int lane = gtid & 31;
    if (n >= NN) return;

    const float2* X = (const float2*)x;     // row = 32 float2
    float dn = g_dinv[n];
    float2 s = X[n * 32 + lane];
    float ax = dn * s.x, ay = dn * s.y;

    int e = g_rowptr[n], end = g_rowptr[n + 1];
    for (; e + 7 < end; e += 8) {
        int si[8];
        #pragma unroll
        for (int u = 0; u < 8; u++) si[u] = g_colsrc[e + u];
        float dv[8];
        #pragma unroll
        for (int u = 0; u < 8; u++) dv[u] = g_dinv[si[u]];
        float2 vv[8];
        #pragma unroll
        for (int u = 0; u < 8; u++) vv[u] = X[si[u] * 32 + lane];
        #pragma unroll
        for (int u = 0; u < 8; u++) {
            ax = fmaf(dv[u], vv[u].x, ax);
            ay = fmaf(dv[u], vv[u].y, ay);
        }
    }
    for (; e < end; e++) {
        int sc = g_colsrc[e];
        float d = g_dinv[sc];
        float2 v = X[sc * 32 + lane];
        ax = fmaf(d, v.x, ax);
        ay = fmaf(d, v.y, ay);
    }
    float2 o; o.x = dn * ax; o.y = dn * ay;
    ((float2*)g_ax)[n * 32 + lane] = o;
}

// -------- GEMM1 (f32x2): a1 = relu(agg_x @ W1 + b1)  (N x 64 @ 64 x 128) ----
__global__ void __launch_bounds__(128) k_gemm1(const float* __restrict__ W1,
                                               const float* __restrict__ b1) {
    __shared__ float sW[F0 * F1];        // 32 KB
    __shared__ float sA[F0 * 36];        // 9 KB, k-major, padded
    int tid = threadIdx.x;
    int n0 = blockIdx.x * 32;

    {
        const float4* Wp = (const float4*)W1;
        float4* Sp = (float4*)sW;
        #pragma unroll
        for (int i = tid; i < F0 * F1 / 4; i += 128) Sp[i] = Wp[i];
    }
    for (int idx = tid; idx < 32 * F0; idx += 128) {
        int j = idx >> 6, k = idx & 63;
        sA[k * 36 + j] = (n0 + j < NN) ? g_ax[(n0 + j) * F0 + k] : 0.f;
    }
    __syncthreads();

    int cg = tid & 15, jg = tid >> 4;    // 16 col-groups x 8 node-groups
    int c0 = cg * 8, j0 = jg * 4;

    unsigned long long acc[4][4];
    #pragma unroll
    for (int a = 0; a < 4; a++)
        #pragma unroll
        for (int b = 0; b < 4; b++) acc[a][b] = 0ULL;

    #pragma unroll 4
    for (int k = 0; k < F0; k++) {
        const ulonglong2* Wp = (const ulonglong2*)&sW[k * F1 + c0];
        ulonglong2 wA = Wp[0], wB = Wp[1];
        float4 av = *(const float4*)&sA[k * 36 + j0];
        unsigned long long a0 = pack2(av.x, av.x);
        unsigned long long a1 = pack2(av.y, av.y);
        unsigned long long a2 = pack2(av.z, av.z);
        unsigned long long a3 = pack2(av.w, av.w);
        ffma2(acc[0][0], a0, wA.x); ffma2(acc[0][1], a0, wA.y);
        ffma2(acc[0][2], a0, wB.x); ffma2(acc[0][3], a0, wB.y);
        ffma2(acc[1][0], a1, wA.x); ffma2(acc[1][1], a1, wA.y);
        ffma2(acc[1][2], a1, wB.x); ffma2(acc[1][3], a1, wB.y);
        ffma2(acc[2][0], a2, wA.x); ffma2(acc[2][1], a2, wA.y);
        ffma2(acc[2][2], a2, wB.x); ffma2(acc[2][3], a2, wB.y);
        ffma2(acc[3][0], a3, wA.x); ffma2(acc[3][1], a3, wA.y);
        ffma2(acc[3][2], a3, wB.x); ffma2(acc[3][3], a3, wB.y);
    }

    float bl[8];
    #pragma unroll
    for (int i = 0; i < 8; i++) bl[i] = __ldg(&b1[c0 + i]);

    #pragma unroll
    for (int jj = 0; jj < 4; jj++) {
        int n = n0 + j0 + jj;
        if (n < NN) {
            float* o = &g_a1[n * F1 + c0];
            #pragma unroll
            for (int p = 0; p < 4; p++) {
                float lo, hi;
                unpack2(acc[jj][p], lo, hi);
                o[2 * p]     = fmaxf(lo + bl[2 * p], 0.f);
                o[2 * p + 1] = fmaxf(hi + bl[2 * p + 1], 0.f);
            }
        }
    }
}

// -------- GEMM2 (f32x2): h2 = a1 @ W2  (N x 128 @ 128 x 32) -----------------
__global__ void __launch_bounds__(128) k_gemm2(const float* __restrict__ W2) {
    __shared__ float sW[F1 * F2];        // 16 KB
    __shared__ float sA[F1 * 36];        // 18 KB
    int tid = threadIdx.x;
    int n0 = blockIdx.x * 32;

    {
        const float4* Wp = (const float4*)W2;
        float4* Sp = (float4*)sW;
        #pragma unroll
        for (int i = tid; i < F1 * F2 / 4; i += 128) Sp[i] = Wp[i];
    }
    for (int idx = tid; idx < 32 * F1; idx += 128) {
        int j = idx >> 7, k = idx & 127;
        sA[k * 36 + j] = (n0 + j < NN) ? g_a1[(n0 + j) * F1 + k] : 0.f;
    }
    __syncthreads();

    int cg = tid & 15, jg = tid >> 4;    // 16 col-groups (2 cols) x 8 node-groups (4)
    int c0 = cg * 2, j0 = jg * 4;

    unsigned long long acc[4];
    #pragma unroll
    for (int a = 0; a < 4; a++) acc[a] = 0ULL;

    #pragma unroll 8
    for (int k = 0; k < F1; k++) {
        unsigned long long w = *(const unsigned long long*)&sW[k * F2 + c0];
        float4 av = *(const float4*)&sA[k * 36 + j0];
        ffma2(acc[0], pack2(av.x, av.x), w);
        ffma2(acc[1], pack2(av.y, av.y), w);
        ffma2(acc[2], pack2(av.z, av.z), w);
        ffma2(acc[3], pack2(av.w, av.w), w);
    }

    #pragma unroll
    for (int jj = 0; jj < 4; jj++) {
        int n = n0 + j0 + jj;
        if (n < NN)
            ((unsigned long long*)g_h2)[n * 16 + cg] = acc[jj];
    }
}

// ------- Fused agg2 + classifier: h = agg(h2)+b2 ; out = h @ Wc + bc --------
__global__ void __launch_bounds__(256) k_agg2g3(const float* __restrict__ b2,
                                                const float* __restrict__ Wc,
                                                const float* __restrict__ bc,
                                                float* __restrict__ out,
                                                float* __restrict__ hout) {
    __shared__ float sW[F2 * F2];        // Wc, 4 KB, [k][c]
    int tid = threadIdx.x;
    for (int i = tid; i < F2 * F2; i += 256) sW[i] = Wc[i];
    __syncthreads();

    int gtid = blockIdx.x * 256 + tid;
    int n = gtid >> 5;
    int lane = gtid & 31;
    if (n >= NN) return;

    float dn = g_dinv[n];
    float acc = dn * g_h2[n * F2 + lane];

    int e = g_rowptr[n], end = g_rowptr[n + 1];
    for (; e + 7 < end; e += 8) {
        int si[8];
        #pragma unroll
        for (int u = 0; u < 8; u++) si[u] = g_colsrc[e + u];
        float dv[8];
        #pragma unroll
        for (int u = 0; u < 8; u++) dv[u] = g_dinv[si[u]];
        float hv[8];
        #pragma unroll
        for (int u = 0; u < 8; u++) hv[u] = g_h2[si[u] * F2 + lane];
        #pragma unroll
        for (int u = 0; u < 8; u++) acc = fmaf(dv[u], hv[u], acc);
    }
    for (; e < end; e++) {
        int s = g_colsrc[e];
        acc = fmaf(g_dinv[s], g_h2[s * F2 + lane], acc);
    }

    float h = dn * acc + b2[lane];
    hout[n * F2 + lane] = h;

    // out[n][lane] = sum_k h[k] * Wc[k][lane] + bc[lane]
    float o = 0.f;
    #pragma unroll
    for (int k = 0; k < F2; k++) {
        float hk = __shfl_sync(0xFFFFFFFFu, h, k);
        o = fmaf(hk, sW[k * F2 + lane], o);
    }
    out[n * F2 + lane] = o + bc[lane];
}

// ---------------- launch -----------------------------------------------------
extern "C" void kernel_launch(void* const* d_in, const int* in_sizes, int n_in,
                              void* d_out, int out_size) {
    const float* x   = (const float*)d_in[0];
    const int*   ei  = (const int*)d_in[1];
    const float* W1  = (const float*)d_in[2];
    const float* b1  = (const float*)d_in[3];
    const float* W2  = (const float*)d_in[4];
    const float* b2  = (const float*)d_in[5];
    const float* Wc  = (const float*)d_in[6];
    const float* bc  = (const float*)d_in[7];

    const int* src = ei;
    const int* dst = ei + NE;

    float* out  = (float*)d_out;            // [NN, F2]
    float* hout = (float*)d_out + NN * F2;  // [NN, F2]

    int nb_nodes = (NN + 255) / 256;
    int nb_edges = (NE + 255) / 256;
    int nb_gemm  = (NN + 31) / 32;

    // CSR build (g_cnt zero at entry; self-zeroed by k_scan1 each run)
    k_count<<<nb_edges, 256>>>(dst);
    k_scan1<<<NBLK, SCAN_B>>>();
    k_scan3<<<nb_nodes, 256>>>();
    k_scatter<<<nb_edges, 256>>>(src, dst);

    // Layer 1 (reordered: aggregate x, then GEMM)
    k_aggx<<<(NN * 32 + 255) / 256, 256>>>(x);
    k_gemm1<<<nb_gemm, 128>>>(W1, b1);

    // Layer 2
    k_gemm2<<<nb_gemm, 128>>>(W2);

    // agg2 + classifier fused
    k_agg2g3<<<(NN * 32 + 255) / 256, 256>>>(b2, Wc, bc, out, hout);
}